// round 13
// baseline (speedup 1.0000x reference)
#include <cuda_runtime.h>
#include <cstdint>
#include <math.h>

#define S_LEN 2048
#define DM    1024
#define NH    16
#define DEPTH 64
#define FF    4096
#define NT    16      // query tiles of 128
#define WIN   384     // band window per query tile

#define MODE_SPLIT 1
#define MODE_PART  2
#define MODE_GELU  3

// fused attention smem layout (floats), all row-major pitch 68
#define RP 68         // row pitch for Q/K/V tiles (68 mod 8 == 4 -> conflict-free float4)
#define SP 396        // score pitch
#define AT_Q_OFF  0                       // Qr[32][68]
#define AT_K_OFF  (32*RP)                 // Kr[128][68] (reused as V chunks [32][68])
#define AT_S_OFF  (32*RP + 128*RP)        // Ss[32][396]
#define AT_SMEM   ((32*RP + 128*RP + 32*SP) * 4)   // 94208 bytes

// ---------------- scratch ----------------
__device__ __align__(256) float g_xn  [S_LEN*DM];
__device__ __align__(256) float g_q   [NH*S_LEN*DEPTH];
__device__ __align__(256) float g_k   [NH*S_LEN*DEPTH];
__device__ __align__(256) float g_v   [NH*S_LEN*DEPTH];
__device__ __align__(256) float g_ctx [S_LEN*DM];
__device__ __align__(256) float g_x2  [S_LEN*DM];
__device__ __align__(256) float g_xn2 [S_LEN*DM];
__device__ __align__(256) float g_h1  [S_LEN*FF];
__device__ __align__(256) float g_part[2*S_LEN*DM];
__device__ __align__(256) float g_wq  [DM*DM];
__device__ __align__(256) float g_wk  [DM*DM];
__device__ __align__(256) float g_wv  [DM*DM];
__device__ __align__(256) float g_wfc [DM*DM];
__device__ __align__(256) float g_wf1 [DM*FF];
__device__ __align__(256) float g_wf2 [FF*DM];

// ---------------- helpers ----------------
__device__ __forceinline__ float f2tf_f(float f) {
    uint32_t r;
    asm("cvt.rna.tf32.f32 %0, %1;" : "=r"(r) : "f"(f));
    return __uint_as_float(r);
}
__device__ __forceinline__ void cp16(uint32_t dst, const void* src) {
    asm volatile("cp.async.cg.shared.global [%0], [%1], 16;\n" :: "r"(dst), "l"(src));
}
__device__ __forceinline__ void mma_tf32(float* d, const uint32_t* a, const uint32_t* b) {
    asm volatile(
        "mma.sync.aligned.m16n8k8.row.col.f32.tf32.tf32.f32 "
        "{%0,%1,%2,%3},{%4,%5,%6,%7},{%8,%9},{%0,%1,%2,%3};\n"
        : "+f"(d[0]), "+f"(d[1]), "+f"(d[2]), "+f"(d[3])
        : "r"(a[0]), "r"(a[1]), "r"(a[2]), "r"(a[3]), "r"(b[0]), "r"(b[1]));
}

// ---------------- merged tf32 rounding of all 6 weights ----------------
__global__ __launch_bounds__(256) void round_all_kernel(
    const float4* __restrict__ iq, const float4* __restrict__ ik, const float4* __restrict__ iv,
    const float4* __restrict__ ifc, const float4* __restrict__ if1, const float4* __restrict__ if2,
    float4* __restrict__ oq, float4* __restrict__ ok, float4* __restrict__ ov,
    float4* __restrict__ ofc, float4* __restrict__ of1, float4* __restrict__ of2)
{
    const int Q1 = DM*DM/4;
    const int F1 = DM*FF/4;
    const int total = 4*Q1 + 2*F1;
    int i = blockIdx.x * 256 + threadIdx.x;
    const int stride = gridDim.x * 256;
    for (; i < total; i += stride) {
        const float4* in; float4* out; int off;
        if (i < 4*Q1) {
            int w = i / Q1; off = i - w*Q1;
            in  = (w==0) ? iq : (w==1) ? ik : (w==2) ? iv : ifc;
            out = (w==0) ? oq : (w==1) ? ok : (w==2) ? ov : ofc;
        } else if (i < 4*Q1 + F1) {
            off = i - 4*Q1; in = if1; out = of1;
        } else {
            off = i - 4*Q1 - F1; in = if2; out = of2;
        }
        float4 v = in[off];
        v.x = f2tf_f(v.x); v.y = f2tf_f(v.y); v.z = f2tf_f(v.z); v.w = f2tf_f(v.w);
        out[off] = v;
    }
}

// ---------------- tf32 GEMM (static smem, TK=16, 2-stage) ----------------
__global__ __launch_bounds__(256, 2) void gemm_tf32(
    const float* __restrict__ A,
    const float* __restrict__ B0, const float* __restrict__ B1, const float* __restrict__ B2,
    const float* __restrict__ bias0, const float* __restrict__ bias1, const float* __restrict__ bias2,
    float* __restrict__ C0, float* __restrict__ C1, float* __restrict__ C2,
    int M, int N, int Ksub, int Kfull, int mode)
{
    __shared__ float As[2][128][20];
    __shared__ float Bs[2][16][136];

    const int tid  = threadIdx.x;
    const int bm   = blockIdx.y * 128;
    const int bn   = blockIdx.x * 128;
    const int z    = blockIdx.z;
    const int warp = tid >> 5, lane = tid & 31;
    const int wm   = (warp & 1) * 64;
    const int wn   = (warp >> 1) * 32;
    const int lq   = lane >> 2, ln = lane & 3;

    const float* B; const float* bias; float* C; int kOff = 0;
    if (mode == MODE_SPLIT) {
        B    = (z == 0) ? B0 : (z == 1) ? B1 : B2;
        bias = (z == 0) ? bias0 : (z == 1) ? bias1 : bias2;
        C    = (z == 0) ? C0 : (z == 1) ? C1 : C2;
    } else if (mode == MODE_PART) {
        B = B0; bias = bias0; C = C0 + (size_t)z * M * N; kOff = z * Ksub;
    } else {
        B = B0; bias = bias0; C = C0;
    }

    uint32_t sA = (uint32_t)__cvta_generic_to_shared(&As[0][0][0]);
    uint32_t sB = (uint32_t)__cvta_generic_to_shared(&Bs[0][0][0]);

    float acc[4][4][4];
#pragma unroll
    for (int i = 0; i < 4; ++i)
#pragma unroll
        for (int j = 0; j < 4; ++j)
#pragma unroll
            for (int e = 0; e < 4; ++e) acc[i][j][e] = 0.0f;

    const int nc = Ksub >> 4;

#define LOADTILES(bu, kof) do {                                                   \
    for (int it = 0; it < 2; ++it) {                                              \
        int idx = tid + (it << 8);                                                \
        int m = idx >> 2; int kq = (idx & 3) << 2;                                \
        cp16(sA + (uint32_t)(((bu)*128 + m)*20 + kq)*4,                           \
             A + (size_t)(bm + m)*Kfull + kOff + (kof) + kq);                     \
    }                                                                             \
    for (int it = 0; it < 2; ++it) {                                              \
        int idx = tid + (it << 8);                                                \
        int kk = idx >> 5; int nq = (idx & 31) << 2;                              \
        cp16(sB + (uint32_t)(((bu)*16 + kk)*136 + nq)*4,                          \
             B + (size_t)(kOff + (kof) + kk)*N + bn + nq);                        \
    }                                                                             \
    asm volatile("cp.async.commit_group;\n" ::);                                  \
} while (0)

    LOADTILES(0, 0);
    for (int c = 0; c < nc; ++c) {
        const int buf = c & 1;
        if (c + 1 < nc) {
            LOADTILES((c + 1) & 1, (c + 1) << 4);
            asm volatile("cp.async.wait_group 1;\n" ::);
        } else {
            asm volatile("cp.async.wait_group 0;\n" ::);
        }
        __syncthreads();

#pragma unroll
        for (int ks = 0; ks < 2; ++ks) {
            const int ko = ks << 3;
            uint32_t af[4][4], bf[4][2];
#pragma unroll
            for (int mt = 0; mt < 4; ++mt) {
                int rm = wm + mt * 16;
                af[mt][0] = __float_as_uint(As[buf][rm + lq    ][ko + ln    ]);
                af[mt][1] = __float_as_uint(As[buf][rm + lq + 8][ko + ln    ]);
                af[mt][2] = __float_as_uint(As[buf][rm + lq    ][ko + ln + 4]);
                af[mt][3] = __float_as_uint(As[buf][rm + lq + 8][ko + ln + 4]);
            }
#pragma unroll
            for (int nt = 0; nt < 4; ++nt) {
                int cn = wn + nt * 8;
                bf[nt][0] = __float_as_uint(Bs[buf][ko + ln    ][cn + lq]);
                bf[nt][1] = __float_as_uint(Bs[buf][ko + ln + 4][cn + lq]);
            }
#pragma unroll
            for (int mt = 0; mt < 4; ++mt)
#pragma unroll
                for (int nt = 0; nt < 4; ++nt)
                    mma_tf32(acc[mt][nt], af[mt], bf[nt]);
        }
        __syncthreads();
    }
#undef LOADTILES

#pragma unroll
    for (int mt = 0; mt < 4; ++mt) {
#pragma unroll
        for (int nt = 0; nt < 4; ++nt) {
#pragma unroll
            for (int e = 0; e < 4; ++e) {
                int row = bm + wm + mt * 16 + lq + ((e >> 1) << 3);
                int col = bn + wn + nt * 8 + (ln << 1) + (e & 1);
                float v = acc[mt][nt][e];
                if (mode == MODE_PART) {
                    C[(size_t)row * N + col] = v;
                } else if (mode == MODE_GELU) {
                    v += bias[col];
                    v = 0.5f * v * (1.0f + erff(v * 0.70710678118654752f));
                    C[(size_t)row * N + col] = f2tf_f(v);
                } else { // MODE_SPLIT
                    v += bias[col];
                    C[(size_t)((col >> 6) * S_LEN + row) * DEPTH + (col & 63)] = v;
                }
            }
        }
    }
}

// ---------------- combine split-K parts ----------------
__global__ __launch_bounds__(256) void combine_kernel(
    const float4* __restrict__ p, const float4* __restrict__ bias,
    const float4* __restrict__ res, float4* __restrict__ out, int n4, int n4cols)
{
    int i = blockIdx.x * 256 + threadIdx.x;
    int stride = gridDim.x * 256;
    for (; i < n4; i += stride) {
        float4 a = p[i], b = p[i + n4], bb = bias[i % n4cols], r = res[i];
        float4 o;
        o.x = a.x + b.x + bb.x + r.x;
        o.y = a.y + b.y + bb.y + r.y;
        o.z = a.z + b.z + bb.z + r.z;
        o.w = a.w + b.w + bb.w + r.w;
        out[i] = o;
    }
}

// ---------------- layernorm ----------------
__global__ __launch_bounds__(256) void ln_kernel(
    const float* __restrict__ x, const float* __restrict__ g,
    const float* __restrict__ b, float* __restrict__ out)
{
    const int row = blockIdx.x, tid = threadIdx.x;
    const int lane = tid & 31, warp = tid >> 5;
    float4 v = *(const float4*)(x + (size_t)row * DM + tid * 4);
    float s  = v.x + v.y + v.z + v.w;
    float ss = v.x * v.x + v.y * v.y + v.z * v.z + v.w * v.w;
#pragma unroll
    for (int o = 16; o; o >>= 1) {
        s  += __shfl_xor_sync(0xffffffffu, s, o);
        ss += __shfl_xor_sync(0xffffffffu, ss, o);
    }
    __shared__ float rs[8], rss[8];
    if (lane == 0) { rs[warp] = s; rss[warp] = ss; }
    __syncthreads();
    float S = 0.f, SS = 0.f;
#pragma unroll
    for (int i = 0; i < 8; ++i) { S += rs[i]; SS += rss[i]; }
    float mu  = S * (1.0f / 1024.0f);
    float var = SS * (1.0f / 1024.0f) - mu * mu;
    float r   = rsqrtf(var + 1e-5f);
    float4 gg = *(const float4*)(g + tid * 4);
    float4 bb = *(const float4*)(b + tid * 4);
    float4 o4;
    o4.x = f2tf_f((v.x - mu) * r * gg.x + bb.x);
    o4.y = f2tf_f((v.y - mu) * r * gg.y + bb.y);
    o4.z = f2tf_f((v.z - mu) * r * gg.z + bb.z);
    o4.w = f2tf_f((v.w - mu) * r * gg.w + bb.w);
    *(float4*)(out + (size_t)row * DM + tid * 4) = o4;
}

// ---------------- fused attention: vectorized fp32, row-major tiles ----------------
__global__ __launch_bounds__(256) void attention_kernel(
    const float* __restrict__ qp, const float* __restrict__ kp,
    const float* __restrict__ vp, float* __restrict__ ctx,
    float* __restrict__ attn, int has_attn)
{
    extern __shared__ float sm[];
    float* Qr = sm + AT_Q_OFF;   // [32][RP] row-major
    float* Kr = sm + AT_K_OFF;   // [128][RP] row-major; reused as V chunks [32][RP]
    float* Ss = sm + AT_S_OFF;   // [32][SP]
    const int tid  = threadIdx.x;
    const int qt = blockIdx.x, t = blockIdx.y, h = blockIdx.z;
    const int r0 = t * 128 + qt * 32;     // query row base (32 rows)
    const int j0 = t * 128 - 128;         // window start
    const int wi = tid >> 5, lane = tid & 31;

    // ---- load Q tile (32 rows x 64 d) row-major, float4 copy ----
#pragma unroll
    for (int u = 0; u < 2; ++u) {
        int idx = tid + (u << 8);          // 0..511
        int r = idx >> 4, q4 = (idx & 15) << 2;
        float4 v = *(const float4*)(qp + (size_t)(h * S_LEN + r0 + r) * DEPTH + q4);
        *(float4*)&Qr[r * RP + q4] = v;
    }

    // ---- scores: 3 column blocks of 128 ----
    for (int cb = 0; cb < 3; ++cb) {
        __syncthreads();
#pragma unroll
        for (int u = 0; u < 8; ++u) {
            int idx = tid + (u << 8);       // 0..2047
            int c = idx >> 4, q4 = (idx & 15) << 2;
            int j = j0 + cb * 128 + c;
            float4 v = make_float4(0.f, 0.f, 0.f, 0.f);
            if (j >= 0 && j < S_LEN)
                v = *(const float4*)(kp + (size_t)(h * S_LEN + j) * DEPTH + q4);
            *(float4*)&Kr[c * RP + q4] = v;
        }
        __syncthreads();

        float acc[4][4];
#pragma unroll
        for (int a = 0; a < 4; ++a)
#pragma unroll
            for (int b = 0; b < 4; ++b) acc[a][b] = 0.f;

#pragma unroll 2
        for (int d4 = 0; d4 < 16; ++d4) {
            float4 q[4];
#pragma unroll
            for (int a = 0; a < 4; ++a)
                q[a] = *(const float4*)&Qr[(wi * 4 + a) * RP + d4 * 4];  // broadcast
#pragma unroll
            for (int b = 0; b < 4; ++b) {
                float4 kv = *(const float4*)&Kr[(lane + 32 * b) * RP + d4 * 4];  // conflict-free
#pragma unroll
                for (int a = 0; a < 4; ++a) {
                    acc[a][b] += q[a].x * kv.x;
                    acc[a][b] += q[a].y * kv.y;
                    acc[a][b] += q[a].z * kv.z;
                    acc[a][b] += q[a].w * kv.w;
                }
            }
        }
#pragma unroll
        for (int a = 0; a < 4; ++a)
#pragma unroll
            for (int b = 0; b < 4; ++b)
                Ss[(wi * 4 + a) * SP + cb * 128 + lane + 32 * b] = acc[a][b] * 0.125f;
    }
    __syncthreads();

    // ---- softmax: warp wi -> rows wi*4..+3; probs written back to Ss ----
#pragma unroll
    for (int rr = 0; rr < 4; ++rr) {
        const int r = wi * 4 + rr;
        const int i = r0 + r;
        float v[12];
        float mx = -3.0e38f;
#pragma unroll
        for (int u = 0; u < 12; ++u) {
            int c = lane + (u << 5);
            int j = j0 + c;
            float s = Ss[r * SP + c];
            if (j < 0 || j >= S_LEN || (i - j) > 128 || (j - i) > 128) s = -1e9f;
            v[u] = s;
            mx = fmaxf(mx, s);
        }
#pragma unroll
        for (int o = 16; o; o >>= 1) mx = fmaxf(mx, __shfl_xor_sync(0xffffffffu, mx, o));
        float sum = 0.f;
#pragma unroll
        for (int u = 0; u < 12; ++u) { v[u] = expf(v[u] - mx); sum += v[u]; }
#pragma unroll
        for (int o = 16; o; o >>= 1) sum += __shfl_xor_sync(0xffffffffu, sum, o);
        const float inv = 1.0f / sum;
#pragma unroll
        for (int u = 0; u < 12; ++u)
            Ss[r * SP + lane + (u << 5)] = v[u] * inv;   // masked -> exactly 0
    }
    __syncthreads();

    // ---- attn output: full 2048-wide rows, pure float4 stores ----
    if (has_attn) {
        for (int u = 0; u < 64; ++u) {
            int idx = tid + (u << 8);
            int r = idx >> 9, c4 = idx & 511;
            int c = c4 << 2;
            int rel = c - j0;
            float4 val = make_float4(0.f, 0.f, 0.f, 0.f);
            if (rel >= 0 && rel < WIN) val = *(const float4*)&Ss[r * SP + rel];
            float4* arow4 = (float4*)(attn + ((size_t)h * S_LEN + r0 + r) * S_LEN);
            arow4[c4] = val;
        }
    }

    // ---- PV: thread = 2 rows x 4 cols; V streamed in 12 chunks of 32 rows ----
    const int rg = tid >> 4;       // 0..15 -> rows rg*2, rg*2+1
    const int cg = tid & 15;       // cols cg*4..+3
    float4 cacc0 = make_float4(0.f, 0.f, 0.f, 0.f);
    float4 cacc1 = make_float4(0.f, 0.f, 0.f, 0.f);

    for (int vb = 0; vb < 12; ++vb) {
        __syncthreads();   // protect Kr/V region reuse
#pragma unroll
        for (int u = 0; u < 2; ++u) {
            int idx = tid + (u << 8);       // 0..511
            int r = idx >> 4, q4 = (idx & 15) << 2;
            int j = j0 + vb * 32 + r;
            float4 v = make_float4(0.f, 0.f, 0.f, 0.f);
            if (j >= 0 && j < S_LEN)
                v = *(const float4*)(vp + (size_t)(h * S_LEN + j) * DEPTH + q4);
            *(float4*)&Kr[r * RP + q4] = v;
        }
        __syncthreads();

#pragma unroll 2
        for (int k4 = 0; k4 < 8; ++k4) {
            float4 p0 = *(const float4*)&Ss[(rg * 2    ) * SP + vb * 32 + k4 * 4];
            float4 p1 = *(const float4*)&Ss[(rg * 2 + 1) * SP + vb * 32 + k4 * 4];
            float pa0[4] = {p0.x, p0.y, p0.z, p0.w};
            float pa1[4] = {p1.x, p1.y, p1.z, p1.w};
#pragma unroll
            for (int kk = 0; kk < 4; ++kk) {
                float4 v = *(const float4*)&Kr[(k4 * 4 + kk) * RP + cg * 4];
                cacc0.x += pa0[kk] * v.x; cacc0.y += pa0[kk] * v.y;
                cacc0.z += pa0[kk] * v.z; cacc0.w += pa0[kk] * v.w;
                cacc1.x += pa1[kk] * v.x; cacc1.y += pa1[kk] * v.y;
                cacc1.z += pa1[kk] * v.z; cacc1.w += pa1[kk] * v.w;
            }
        }
    }

    {
        float4 o0, o1;
        o0.x = f2tf_f(cacc0.x); o0.y = f2tf_f(cacc0.y);
        o0.z = f2tf_f(cacc0.z); o0.w = f2tf_f(cacc0.w);
        o1.x = f2tf_f(cacc1.x); o1.y = f2tf_f(cacc1.y);
        o1.z = f2tf_f(cacc1.z); o1.w = f2tf_f(cacc1.w);
        *(float4*)(ctx + (size_t)(r0 + rg * 2    ) * DM + h * DEPTH + cg * 4) = o0;
        *(float4*)(ctx + (size_t)(r0 + rg * 2 + 1) * DM + h * DEPTH + cg * 4) = o1;
    }
}

// ---------------- launch ----------------
extern "C" void kernel_launch(void* const* d_in, const int* in_sizes, int n_in,
                              void* d_out, int out_size)
{
    const float* x    = (const float*)d_in[0];
    const float* wqw  = (const float*)d_in[1];
    const float* wqb  = (const float*)d_in[2];
    const float* wkw  = (const float*)d_in[3];
    const float* wkb  = (const float*)d_in[4];
    const float* wvw  = (const float*)d_in[5];
    const float* wvb  = (const float*)d_in[6];
    const float* fcw  = (const float*)d_in[7];
    const float* fcb  = (const float*)d_in[8];
    const float* ff1w = (const float*)d_in[9];
    const float* ff1b = (const float*)d_in[10];
    const float* ff2w = (const float*)d_in[11];
    const float* ff2b = (const float*)d_in[12];
    const float* ln1g = (const float*)d_in[13];
    const float* ln1b = (const float*)d_in[14];
    const float* ln2g = (const float*)d_in[15];
    const float* ln2b = (const float*)d_in[16];

    float* out = (float*)d_out;
    const int has_attn = (out_size > S_LEN * DM) ? 1 : 0;
    float* attn = out + (size_t)S_LEN * DM;

    float *xn, *q, *k, *v, *ctx, *x2, *xn2, *h1, *part;
    float *wq, *wk, *wv, *wfc, *wf1, *wf2;
    cudaGetSymbolAddress((void**)&xn,  g_xn);
    cudaGetSymbolAddress((void**)&q,   g_q);
    cudaGetSymbolAddress((void**)&k,   g_k);
    cudaGetSymbolAddress((void**)&v,   g_v);
    cudaGetSymbolAddress((void**)&ctx, g_ctx);
    cudaGetSymbolAddress((void**)&x2,  g_x2);
    cudaGetSymbolAddress((void**)&xn2, g_xn2);
    cudaGetSymbolAddress((void**)&h1,  g_h1);
    cudaGetSymbolAddress((void**)&part, g_part);
    cudaGetSymbolAddress((void**)&wq,  g_wq);
    cudaGetSymbolAddress((void**)&wk,  g_wk);
    cudaGetSymbolAddress((void**)&wv,  g_wv);
    cudaGetSymbolAddress((void**)&wfc, g_wfc);
    cudaGetSymbolAddress((void**)&wf1, g_wf1);
    cudaGetSymbolAddress((void**)&wf2, g_wf2);

    cudaFuncSetAttribute(attention_kernel,
                         cudaFuncAttributeMaxDynamicSharedMemorySize, AT_SMEM);

    // #1: merged weight rounding
    round_all_kernel<<<2048, 256>>>(
        (const float4*)wqw, (const float4*)wkw, (const float4*)wvw,
        (const float4*)fcw, (const float4*)ff1w, (const float4*)ff2w,
        (float4*)wq, (float4*)wk, (float4*)wv, (float4*)wfc, (float4*)wf1, (float4*)wf2);

    // #2
    ln_kernel<<<S_LEN, 256>>>(x, ln1g, ln1b, xn);

    // #3: fused QKV GEMM
    gemm_tf32<<<dim3(DM/128, S_LEN/128, 3), 256>>>(
        xn, wq, wk, wv, wqb, wkb, wvb, q, k, v, S_LEN, DM, DM, DM, MODE_SPLIT);

    // #4: fused attention (scores + softmax + attn write + PV)
    attention_kernel<<<dim3(4, NT, NH), 256, AT_SMEM>>>(q, k, v, ctx, attn, has_attn);

    // #5: fc split-K=2 + combine with residual x
    gemm_tf32<<<dim3(DM/128, S_LEN/128, 2), 256>>>(
        ctx, wfc, wfc, wfc, fcb, fcb, fcb, part, part, part,
        S_LEN, DM, DM/2, DM, MODE_PART);
    combine_kernel<<<1024, 256>>>((const float4*)part, (const float4*)fcb,
                                  (const float4*)x, (float4*)x2, S_LEN*DM/4, DM/4);

    ln_kernel<<<S_LEN, 256>>>(x2, ln2g, ln2b, xn2);

    // ff1 + gelu
    gemm_tf32<<<dim3(FF/128, S_LEN/128, 1), 256>>>(
        xn2, wf1, wf1, wf1, ff1b, ff1b, ff1b, h1, h1, h1,
        S_LEN, FF, DM, DM, MODE_GELU);

    // ff2 split-K=2 + combine -> final out
    gemm_tf32<<<dim3(DM/128, S_LEN/128, 2), 256>>>(
        h1, wf2, wf2, wf2, ff2b, ff2b, ff2b, part, part, part,
        S_LEN, DM, FF/2, FF, MODE_PART);
    combine_kernel<<<1024, 256>>>((const float4*)part, (const float4*)ff2b,
                                  (const float4*)x2, (float4*)out, S_LEN*DM/4, DM/4);
}

// round 15
// speedup vs baseline: 1.1161x; 1.1161x over previous
#include <cuda_runtime.h>
#include <cstdint>
#include <math.h>

#define S_LEN 2048
#define DM    1024
#define NH    16
#define DEPTH 64
#define FF    4096
#define NT    16      // query tiles of 128
#define WIN   384     // band window per query tile

#define MODE_SPLIT 1
#define MODE_PART  2
#define MODE_GELU  3

// fused attention smem layout (floats)
#define RP 68         // Q/K/V row pitch (16B-aligned rows, conflict-free ldmatrix)
#define SP 396        // score pitch (16B-aligned rows, conflict-free ldmatrix)
#define AT_Q_OFF  0                       // Qr[32][68]
#define AT_K_OFF  (32*RP)                 // Kr[128][68] (reused as V chunks [128][68])
#define AT_S_OFF  (32*RP + 128*RP)        // Ss[32][396]
#define AT_SMEM   ((32*RP + 128*RP + 32*SP) * 4)   // 94208 bytes

// ---------------- scratch ----------------
__device__ __align__(256) float g_xn  [S_LEN*DM];
__device__ __align__(256) float g_q   [NH*S_LEN*DEPTH];
__device__ __align__(256) float g_k   [NH*S_LEN*DEPTH];
__device__ __align__(256) float g_v   [NH*S_LEN*DEPTH];
__device__ __align__(256) float g_ctx [S_LEN*DM];
__device__ __align__(256) float g_x2  [S_LEN*DM];
__device__ __align__(256) float g_xn2 [S_LEN*DM];
__device__ __align__(256) float g_h1  [S_LEN*FF];
__device__ __align__(256) float g_part[2*S_LEN*DM];
__device__ __align__(256) float g_wq  [DM*DM];
__device__ __align__(256) float g_wk  [DM*DM];
__device__ __align__(256) float g_wv  [DM*DM];
__device__ __align__(256) float g_wfc [DM*DM];
__device__ __align__(256) float g_wf1 [DM*FF];
__device__ __align__(256) float g_wf2 [FF*DM];

// ---------------- helpers ----------------
__device__ __forceinline__ float f2tf_f(float f) {
    uint32_t r;
    asm("cvt.rna.tf32.f32 %0, %1;" : "=r"(r) : "f"(f));
    return __uint_as_float(r);
}
__device__ __forceinline__ void cp16(uint32_t dst, const void* src) {
    asm volatile("cp.async.cg.shared.global [%0], [%1], 16;\n" :: "r"(dst), "l"(src));
}
__device__ __forceinline__ void mma_tf32(float* d, const uint32_t* a, const uint32_t* b) {
    asm volatile(
        "mma.sync.aligned.m16n8k8.row.col.f32.tf32.tf32.f32 "
        "{%0,%1,%2,%3},{%4,%5,%6,%7},{%8,%9},{%0,%1,%2,%3};\n"
        : "+f"(d[0]), "+f"(d[1]), "+f"(d[2]), "+f"(d[3])
        : "r"(a[0]), "r"(a[1]), "r"(a[2]), "r"(a[3]), "r"(b[0]), "r"(b[1]));
}
__device__ __forceinline__ void ldsm_x4(uint32_t* r, uint32_t addr) {
    asm volatile("ldmatrix.sync.aligned.m8n8.x4.shared.b16 {%0,%1,%2,%3}, [%4];"
        : "=r"(r[0]), "=r"(r[1]), "=r"(r[2]), "=r"(r[3]) : "r"(addr));
}
__device__ __forceinline__ void ldsm_x2(uint32_t* r, uint32_t addr) {
    asm volatile("ldmatrix.sync.aligned.m8n8.x2.shared.b16 {%0,%1}, [%2];"
        : "=r"(r[0]), "=r"(r[1]) : "r"(addr));
}

// ---------------- merged tf32 rounding of all 6 weights ----------------
__global__ __launch_bounds__(256) void round_all_kernel(
    const float4* __restrict__ iq, const float4* __restrict__ ik, const float4* __restrict__ iv,
    const float4* __restrict__ ifc, const float4* __restrict__ if1, const float4* __restrict__ if2,
    float4* __restrict__ oq, float4* __restrict__ ok, float4* __restrict__ ov,
    float4* __restrict__ ofc, float4* __restrict__ of1, float4* __restrict__ of2)
{
    const int Q1 = DM*DM/4;
    const int F1 = DM*FF/4;
    const int total = 4*Q1 + 2*F1;
    int i = blockIdx.x * 256 + threadIdx.x;
    const int stride = gridDim.x * 256;
    for (; i < total; i += stride) {
        const float4* in; float4* out; int off;
        if (i < 4*Q1) {
            int w = i / Q1; off = i - w*Q1;
            in  = (w==0) ? iq : (w==1) ? ik : (w==2) ? iv : ifc;
            out = (w==0) ? oq : (w==1) ? ok : (w==2) ? ov : ofc;
        } else if (i < 4*Q1 + F1) {
            off = i - 4*Q1; in = if1; out = of1;
        } else {
            off = i - 4*Q1 - F1; in = if2; out = of2;
        }
        float4 v = in[off];
        v.x = f2tf_f(v.x); v.y = f2tf_f(v.y); v.z = f2tf_f(v.z); v.w = f2tf_f(v.w);
        out[off] = v;
    }
}

// ---------------- tf32 GEMM (static smem, TK=16, 2-stage) ----------------
__global__ __launch_bounds__(256, 2) void gemm_tf32(
    const float* __restrict__ A,
    const float* __restrict__ B0, const float* __restrict__ B1, const float* __restrict__ B2,
    const float* __restrict__ bias0, const float* __restrict__ bias1, const float* __restrict__ bias2,
    float* __restrict__ C0, float* __restrict__ C1, float* __restrict__ C2,
    int M, int N, int Ksub, int Kfull, int mode)
{
    __shared__ float As[2][128][20];
    __shared__ float Bs[2][16][136];

    const int tid  = threadIdx.x;
    const int bm   = blockIdx.y * 128;
    const int bn   = blockIdx.x * 128;
    const int z    = blockIdx.z;
    const int warp = tid >> 5, lane = tid & 31;
    const int wm   = (warp & 1) * 64;
    const int wn   = (warp >> 1) * 32;
    const int lq   = lane >> 2, ln = lane & 3;

    const float* B; const float* bias; float* C; int kOff = 0;
    if (mode == MODE_SPLIT) {
        B    = (z == 0) ? B0 : (z == 1) ? B1 : B2;
        bias = (z == 0) ? bias0 : (z == 1) ? bias1 : bias2;
        C    = (z == 0) ? C0 : (z == 1) ? C1 : C2;
    } else if (mode == MODE_PART) {
        B = B0; bias = bias0; C = C0 + (size_t)z * M * N; kOff = z * Ksub;
    } else {
        B = B0; bias = bias0; C = C0;
    }

    uint32_t sA = (uint32_t)__cvta_generic_to_shared(&As[0][0][0]);
    uint32_t sB = (uint32_t)__cvta_generic_to_shared(&Bs[0][0][0]);

    float acc[4][4][4];
#pragma unroll
    for (int i = 0; i < 4; ++i)
#pragma unroll
        for (int j = 0; j < 4; ++j)
#pragma unroll
            for (int e = 0; e < 4; ++e) acc[i][j][e] = 0.0f;

    const int nc = Ksub >> 4;

#define LOADTILES(bu, kof) do {                                                   \
    for (int it = 0; it < 2; ++it) {                                              \
        int idx = tid + (it << 8);                                                \
        int m = idx >> 2; int kq = (idx & 3) << 2;                                \
        cp16(sA + (uint32_t)(((bu)*128 + m)*20 + kq)*4,                           \
             A + (size_t)(bm + m)*Kfull + kOff + (kof) + kq);                     \
    }                                                                             \
    for (int it = 0; it < 2; ++it) {                                              \
        int idx = tid + (it << 8);                                                \
        int kk = idx >> 5; int nq = (idx & 31) << 2;                              \
        cp16(sB + (uint32_t)(((bu)*16 + kk)*136 + nq)*4,                          \
             B + (size_t)(kOff + (kof) + kk)*N + bn + nq);                        \
    }                                                                             \
    asm volatile("cp.async.commit_group;\n" ::);                                  \
} while (0)

    LOADTILES(0, 0);
    for (int c = 0; c < nc; ++c) {
        const int buf = c & 1;
        if (c + 1 < nc) {
            LOADTILES((c + 1) & 1, (c + 1) << 4);
            asm volatile("cp.async.wait_group 1;\n" ::);
        } else {
            asm volatile("cp.async.wait_group 0;\n" ::);
        }
        __syncthreads();

#pragma unroll
        for (int ks = 0; ks < 2; ++ks) {
            const int ko = ks << 3;
            uint32_t af[4][4], bf[4][2];
#pragma unroll
            for (int mt = 0; mt < 4; ++mt) {
                int rm = wm + mt * 16;
                af[mt][0] = __float_as_uint(As[buf][rm + lq    ][ko + ln    ]);
                af[mt][1] = __float_as_uint(As[buf][rm + lq + 8][ko + ln    ]);
                af[mt][2] = __float_as_uint(As[buf][rm + lq    ][ko + ln + 4]);
                af[mt][3] = __float_as_uint(As[buf][rm + lq + 8][ko + ln + 4]);
            }
#pragma unroll
            for (int nt = 0; nt < 4; ++nt) {
                int cn = wn + nt * 8;
                bf[nt][0] = __float_as_uint(Bs[buf][ko + ln    ][cn + lq]);
                bf[nt][1] = __float_as_uint(Bs[buf][ko + ln + 4][cn + lq]);
            }
#pragma unroll
            for (int mt = 0; mt < 4; ++mt)
#pragma unroll
                for (int nt = 0; nt < 4; ++nt)
                    mma_tf32(acc[mt][nt], af[mt], bf[nt]);
        }
        __syncthreads();
    }
#undef LOADTILES

#pragma unroll
    for (int mt = 0; mt < 4; ++mt) {
#pragma unroll
        for (int nt = 0; nt < 4; ++nt) {
#pragma unroll
            for (int e = 0; e < 4; ++e) {
                int row = bm + wm + mt * 16 + lq + ((e >> 1) << 3);
                int col = bn + wn + nt * 8 + (ln << 1) + (e & 1);
                float v = acc[mt][nt][e];
                if (mode == MODE_PART) {
                    C[(size_t)row * N + col] = v;
                } else if (mode == MODE_GELU) {
                    v += bias[col];
                    v = 0.5f * v * (1.0f + erff(v * 0.70710678118654752f));
                    C[(size_t)row * N + col] = f2tf_f(v);
                } else { // MODE_SPLIT: tf32-rounded store for mma-based attention
                    v += bias[col];
                    C[(size_t)((col >> 6) * S_LEN + row) * DEPTH + (col & 63)] = f2tf_f(v);
                }
            }
        }
    }
}

// ---------------- combine split-K parts ----------------
__global__ __launch_bounds__(256) void combine_kernel(
    const float4* __restrict__ p, const float4* __restrict__ bias,
    const float4* __restrict__ res, float4* __restrict__ out, int n4, int n4cols)
{
    int i = blockIdx.x * 256 + threadIdx.x;
    int stride = gridDim.x * 256;
    for (; i < n4; i += stride) {
        float4 a = p[i], b = p[i + n4], bb = bias[i % n4cols], r = res[i];
        float4 o;
        o.x = a.x + b.x + bb.x + r.x;
        o.y = a.y + b.y + bb.y + r.y;
        o.z = a.z + b.z + bb.z + r.z;
        o.w = a.w + b.w + bb.w + r.w;
        out[i] = o;
    }
}

// ---------------- layernorm ----------------
__global__ __launch_bounds__(256) void ln_kernel(
    const float* __restrict__ x, const float* __restrict__ g,
    const float* __restrict__ b, float* __restrict__ out)
{
    const int row = blockIdx.x, tid = threadIdx.x;
    const int lane = tid & 31, warp = tid >> 5;
    float4 v = *(const float4*)(x + (size_t)row * DM + tid * 4);
    float s  = v.x + v.y + v.z + v.w;
    float ss = v.x * v.x + v.y * v.y + v.z * v.z + v.w * v.w;
#pragma unroll
    for (int o = 16; o; o >>= 1) {
        s  += __shfl_xor_sync(0xffffffffu, s, o);
        ss += __shfl_xor_sync(0xffffffffu, ss, o);
    }
    __shared__ float rs[8], rss[8];
    if (lane == 0) { rs[warp] = s; rss[warp] = ss; }
    __syncthreads();
    float S = 0.f, SS = 0.f;
#pragma unroll
    for (int i = 0; i < 8; ++i) { S += rs[i]; SS += rss[i]; }
    float mu  = S * (1.0f / 1024.0f);
    float var = SS * (1.0f / 1024.0f) - mu * mu;
    float r   = rsqrtf(var + 1e-5f);
    float4 gg = *(const float4*)(g + tid * 4);
    float4 bb = *(const float4*)(b + tid * 4);
    float4 o4;
    o4.x = f2tf_f((v.x - mu) * r * gg.x + bb.x);
    o4.y = f2tf_f((v.y - mu) * r * gg.y + bb.y);
    o4.z = f2tf_f((v.z - mu) * r * gg.z + bb.z);
    o4.w = f2tf_f((v.w - mu) * r * gg.w + bb.w);
    *(float4*)(out + (size_t)row * DM + tid * 4) = o4;
}

// ---------------- fused attention via tensor-core mma ----------------
__global__ __launch_bounds__(256) void attention_kernel(
    const float* __restrict__ qp, const float* __restrict__ kp,
    const float* __restrict__ vp, float* __restrict__ ctx,
    float* __restrict__ attn, int has_attn)
{
    extern __shared__ float sm[];
    float* Qr = sm + AT_Q_OFF;   // [32][RP]  (tf32 values)
    float* Kr = sm + AT_K_OFF;   // [128][RP] (tf32); reused as V chunks
    float* Ss = sm + AT_S_OFF;   // [32][SP]
    const int tid  = threadIdx.x;
    const int qt = blockIdx.x, t = blockIdx.y, h = blockIdx.z;
    const int r0 = t * 128 + qt * 32;
    const int j0 = t * 128 - 128;
    const int wi = tid >> 5, lane = tid & 31;

    const uint32_t smQ = (uint32_t)__cvta_generic_to_shared(Qr);
    const uint32_t smK = (uint32_t)__cvta_generic_to_shared(Kr);
    const uint32_t smS = (uint32_t)__cvta_generic_to_shared(Ss);

    // per-lane ldmatrix address components
    const int lr8  = lane & 7;
    const int arow = lr8 + ((lane >> 3) & 1) * 8;     // x4: row within m16
    const int acol = ((lane >> 4) & 1) * 4;           // x4: k quadrant
    const int bcol = ((lane >> 3) & 1) * 4;           // x2: k quadrant (lanes 0-15)

    // ---- load Q tile (32 x 64), already tf32 ----
#pragma unroll
    for (int u = 0; u < 2; ++u) {
        int idx = tid + (u << 8);
        int r = idx >> 4, q4 = (idx & 15) << 2;
        *(float4*)&Qr[r * RP + q4] =
            *(const float4*)(qp + (size_t)(h * S_LEN + r0 + r) * DEPTH + q4);
    }

    // ---- scores: 3 K-blocks of 128 cols; warp covers 16 cols per block ----
    for (int cb = 0; cb < 3; ++cb) {
        __syncthreads();
#pragma unroll
        for (int u = 0; u < 8; ++u) {
            int idx = tid + (u << 8);
            int c = idx >> 4, q4 = (idx & 15) << 2;
            int j = j0 + cb * 128 + c;
            float4 v = make_float4(0.f, 0.f, 0.f, 0.f);
            if (j >= 0 && j < S_LEN)
                v = *(const float4*)(kp + (size_t)(h * S_LEN + j) * DEPTH + q4);
            *(float4*)&Kr[c * RP + q4] = v;
        }
        __syncthreads();

        float sacc[2][2][4];
#pragma unroll
        for (int mt = 0; mt < 2; ++mt)
#pragma unroll
            for (int nt = 0; nt < 2; ++nt)
#pragma unroll
                for (int e = 0; e < 4; ++e) sacc[mt][nt][e] = 0.f;

#pragma unroll
        for (int ks = 0; ks < 8; ++ks) {
            const int ko = ks * 8;
            uint32_t a[2][4], b[2][2];
#pragma unroll
            for (int mt = 0; mt < 2; ++mt)
                ldsm_x4(a[mt], smQ + (uint32_t)((mt * 16 + arow) * RP + ko + acol) * 4);
#pragma unroll
            for (int nt = 0; nt < 2; ++nt)
                ldsm_x2(b[nt], smK + (uint32_t)((wi * 16 + nt * 8 + lr8) * RP + ko + bcol) * 4);
#pragma unroll
            for (int mt = 0; mt < 2; ++mt)
#pragma unroll
                for (int nt = 0; nt < 2; ++nt)
                    mma_tf32(sacc[mt][nt], a[mt], b[nt]);
        }
#pragma unroll
        for (int mt = 0; mt < 2; ++mt) {
#pragma unroll
            for (int nt = 0; nt < 2; ++nt) {
                int gcol = cb * 128 + wi * 16 + nt * 8 + 2 * (lane & 3);
                int row  = mt * 16 + (lane >> 2);
                Ss[row * SP + gcol]           = sacc[mt][nt][0] * 0.125f;
                Ss[row * SP + gcol + 1]       = sacc[mt][nt][1] * 0.125f;
                Ss[(row + 8) * SP + gcol]     = sacc[mt][nt][2] * 0.125f;
                Ss[(row + 8) * SP + gcol + 1] = sacc[mt][nt][3] * 0.125f;
            }
        }
    }
    __syncthreads();

    // ---- softmax: warp wi -> rows wi*4..+3; probs back into Ss (fp32) ----
#pragma unroll
    for (int rr = 0; rr < 4; ++rr) {
        const int r = wi * 4 + rr;
        const int i = r0 + r;
        float v[12];
        float mx = -3.0e38f;
#pragma unroll
        for (int u = 0; u < 12; ++u) {
            int c = lane + (u << 5);
            int j = j0 + c;
            float s = Ss[r * SP + c];
            if (j < 0 || j >= S_LEN || (i - j) > 128 || (j - i) > 128) s = -1e9f;
            v[u] = s;
            mx = fmaxf(mx, s);
        }
#pragma unroll
        for (int o = 16; o; o >>= 1) mx = fmaxf(mx, __shfl_xor_sync(0xffffffffu, mx, o));
        float sum = 0.f;
#pragma unroll
        for (int u = 0; u < 12; ++u) { v[u] = expf(v[u] - mx); sum += v[u]; }
#pragma unroll
        for (int o = 16; o; o >>= 1) sum += __shfl_xor_sync(0xffffffffu, sum, o);
        const float inv = 1.0f / sum;
#pragma unroll
        for (int u = 0; u < 12; ++u)
            Ss[r * SP + lane + (u << 5)] = v[u] * inv;   // masked -> exactly 0
    }
    __syncthreads();

    // ---- attn output: full 2048-wide rows, float4 stores (fp32 probs) ----
    if (has_attn) {
        for (int u = 0; u < 64; ++u) {
            int idx = tid + (u << 8);
            int r = idx >> 9, c4 = idx & 511;
            int c = c4 << 2;
            int rel = c - j0;
            float4 val = make_float4(0.f, 0.f, 0.f, 0.f);
            if (rel >= 0 && rel < WIN) val = *(const float4*)&Ss[r * SP + rel];
            float4* arow4 = (float4*)(attn + ((size_t)h * S_LEN + r0 + r) * S_LEN);
            arow4[c4] = val;
        }
    }
    __syncthreads();

    // ---- round probs in Ss to tf32 for the PV mma ----
#pragma unroll
    for (int u = 0; u < 12; ++u) {
        int idx = tid + (u << 8);
        int r = idx / 96, c4 = idx % 96;
        float4* p = (float4*)&Ss[r * SP + (c4 << 2)];
        float4 v = *p;
        v.x = f2tf_f(v.x); v.y = f2tf_f(v.y); v.z = f2tf_f(v.z); v.w = f2tf_f(v.w);
        *p = v;
    }

    // ---- PV via mma: ctx[32x64] = P[32x384] @ V[384x64]; warp -> 8 cols ----
    float pacc[2][4];
#pragma unroll
    for (int mt = 0; mt < 2; ++mt)
#pragma unroll
        for (int e = 0; e < 4; ++e) pacc[mt][e] = 0.f;

    for (int vb = 0; vb < 3; ++vb) {
        __syncthreads();   // Ss round done (vb=0) / previous chunk consumed
#pragma unroll
        for (int u = 0; u < 8; ++u) {
            int idx = tid + (u << 8);
            int r = idx >> 4, q4 = (idx & 15) << 2;
            int j = j0 + vb * 128 + r;
            float4 v = make_float4(0.f, 0.f, 0.f, 0.f);
            if (j >= 0 && j < S_LEN)
                v = *(const float4*)(vp + (size_t)(h * S_LEN + j) * DEPTH + q4);
            *(float4*)&Kr[r * RP + q4] = v;
        }
        __syncthreads();

#pragma unroll
        for (int ks = 0; ks < 16; ++ks) {
            const int kos = vb * 128 + ks * 8;   // column in Ss
            const int kr  = ks * 8;              // row in V chunk
            uint32_t a[2][4], b[2];
#pragma unroll
            for (int mt = 0; mt < 2; ++mt)
                ldsm_x4(a[mt], smS + (uint32_t)((mt * 16 + arow) * SP + kos + acol) * 4);
            b[0] = __float_as_uint(Kr[(kr +     (lane & 3)) * RP + wi * 8 + (lane >> 2)]);
            b[1] = __float_as_uint(Kr[(kr + 4 + (lane & 3)) * RP + wi * 8 + (lane >> 2)]);
#pragma unroll
            for (int mt = 0; mt < 2; ++mt)
                mma_tf32(pacc[mt], a[mt], b);
        }
    }

#pragma unroll
    for (int mt = 0; mt < 2; ++mt) {
        int row = r0 + mt * 16 + (lane >> 2);
        int col = h * DEPTH + wi * 8 + 2 * (lane & 3);
        float2 o0, o1;
        o0.x = f2tf_f(pacc[mt][0]); o0.y = f2tf_f(pacc[mt][1]);
        o1.x = f2tf_f(pacc[mt][2]); o1.y = f2tf_f(pacc[mt][3]);
        *(float2*)(ctx + (size_t)row * DM + col) = o0;
        *(float2*)(ctx + (size_t)(row + 8) * DM + col) = o1;
    }
}

// ---------------- launch ----------------
extern "C" void kernel_launch(void* const* d_in, const int* in_sizes, int n_in,
                              void* d_out, int out_size)
{
    const float* x    = (const float*)d_in[0];
    const float* wqw  = (const float*)d_in[1];
    const float* wqb  = (const float*)d_in[2];
    const float* wkw  = (const float*)d_in[3];
    const float* wkb  = (const float*)d_in[4];
    const float* wvw  = (const float*)d_in[5];
    const float* wvb  = (const float*)d_in[6];
    const float* fcw  = (const float*)d_in[7];
    const float* fcb  = (const float*)d_in[8];
    const float* ff1w = (const float*)d_in[9];
    const float* ff1b = (const float*)d_in[10];
    const float* ff2w = (const float*)d_in[11];
    const float* ff2b = (const float*)d_in[12];
    const float* ln1g = (const float*)d_in[13];
    const float* ln1b = (const float*)d_in[14];
    const float* ln2g = (const float*)d_in[15];
    const float* ln2b = (const float*)d_in[16];

    float* out = (float*)d_out;
    const int has_attn = (out_size > S_LEN * DM) ? 1 : 0;
    float* attn = out + (size_t)S_LEN * DM;

    float *xn, *q, *k, *v, *ctx, *x2, *xn2, *h1, *part;
    float *wq, *wk, *wv, *wfc, *wf1, *wf2;
    cudaGetSymbolAddress((void**)&xn,  g_xn);
    cudaGetSymbolAddress((void**)&q,   g_q);
    cudaGetSymbolAddress((void**)&k,   g_k);
    cudaGetSymbolAddress((void**)&v,   g_v);
    cudaGetSymbolAddress((void**)&ctx, g_ctx);
    cudaGetSymbolAddress((void**)&x2,  g_x2);
    cudaGetSymbolAddress((void**)&xn2, g_xn2);
    cudaGetSymbolAddress((void**)&h1,  g_h1);
    cudaGetSymbolAddress((void**)&part, g_part);
    cudaGetSymbolAddress((void**)&wq,  g_wq);
    cudaGetSymbolAddress((void**)&wk,  g_wk);
    cudaGetSymbolAddress((void**)&wv,  g_wv);
    cudaGetSymbolAddress((void**)&wfc, g_wfc);
    cudaGetSymbolAddress((void**)&wf1, g_wf1);
    cudaGetSymbolAddress((void**)&wf2, g_wf2);

    cudaFuncSetAttribute(attention_kernel,
                         cudaFuncAttributeMaxDynamicSharedMemorySize, AT_SMEM);

    // #1: merged weight rounding
    round_all_kernel<<<2048, 256>>>(
        (const float4*)wqw, (const float4*)wkw, (const float4*)wvw,
        (const float4*)fcw, (const float4*)ff1w, (const float4*)ff2w,
        (float4*)wq, (float4*)wk, (float4*)wv, (float4*)wfc, (float4*)wf1, (float4*)wf2);

    // #2
    ln_kernel<<<S_LEN, 256>>>(x, ln1g, ln1b, xn);

    // #3: fused QKV GEMM (tf32-rounded q/k/v outputs)
    gemm_tf32<<<dim3(DM/128, S_LEN/128, 3), 256>>>(
        xn, wq, wk, wv, wqb, wkb, wvb, q, k, v, S_LEN, DM, DM, DM, MODE_SPLIT);

    // #4: fused attention via mma (scores + softmax + attn write + PV)
    attention_kernel<<<dim3(4, NT, NH), 256, AT_SMEM>>>(q, k, v, ctx, attn, has_attn);

    // #5: fc split-K=2 + combine with residual x
    gemm_tf32<<<dim3(DM/128, S_LEN/128, 2), 256>>>(
        ctx, wfc, wfc, wfc, fcb, fcb, fcb, part, part, part,
        S_LEN, DM, DM/2, DM, MODE_PART);
    combine_kernel<<<1024, 256>>>((const float4*)part, (const float4*)fcb,
                                  (const float4*)x, (float4*)x2, S_LEN*DM/4, DM/4);

    ln_kernel<<<S_LEN, 256>>>(x2, ln2g, ln2b, xn2);

    // ff1 + gelu
    gemm_tf32<<<dim3(FF/128, S_LEN/128, 1), 256>>>(
        xn2, wf1, wf1, wf1, ff1b, ff1b, ff1b, h1, h1, h1,
        S_LEN, FF, DM, DM, MODE_GELU);

    // ff2 split-K=2 + combine -> final out
    gemm_tf32<<<dim3(DM/128, S_LEN/128, 2), 256>>>(
        h1, wf2, wf2, wf2, ff2b, ff2b, ff2b, part, part, part,
        S_LEN, DM, FF/2, FF, MODE_PART);
    combine_kernel<<<1024, 256>>>((const float4*)part, (const float4*)ff2b,
                                  (const float4*)x2, (float4*)out, S_LEN*DM/4, DM/4);
}